// round 10
// baseline (speedup 1.0000x reference)
#include <cuda_runtime.h>
#include <cuda_fp16.h>

#define HH 128
#define WW 128
#define PLANE (HH*WW)
#define CYC 21
#define TW 16
#define TH 8
#define HLW 26              // halo cols: tw0-5 .. tw0+20
#define HLH 13              // halo rows: th0 .. th0+12
#define NC (HLW*HLH)        // 338
#define NT 256              // 64 pixel-pairs x 4 cell-groups
#define NBLK 512            // 8*16*4

typedef unsigned long long u64;
typedef unsigned int u32;

__device__ float g_part[NBLK];
__device__ unsigned int g_cnt = 0;

__device__ __forceinline__ u64 pack2(float lo, float hi) {
    u64 r; asm("mov.b64 %0,{%1,%2};" : "=l"(r) : "f"(lo), "f"(hi)); return r;
}
__device__ __forceinline__ void unpack2(u64 v, float& lo, float& hi) {
    asm("mov.b64 {%0,%1},%2;" : "=f"(lo), "=f"(hi) : "l"(v));
}
__device__ __forceinline__ u64 add2(u64 a, u64 b) {
    u64 d; asm("add.rn.f32x2 %0,%1,%2;" : "=l"(d) : "l"(a), "l"(b)); return d;
}
__device__ __forceinline__ u64 mul2(u64 a, u64 b) {
    u64 d; asm("mul.rn.f32x2 %0,%1,%2;" : "=l"(d) : "l"(a), "l"(b)); return d;
}
__device__ __forceinline__ u64 ffma2(u64 a, u64 b, u64 c) {
    u64 d; asm("fma.rn.f32x2 %0,%1,%2,%3;" : "=l"(d) : "l"(a), "l"(b), "l"(c)); return d;
}
__device__ __forceinline__ float ex2(float v) {
    float r; asm("ex2.approx.ftz.f32 %0,%1;" : "=f"(r) : "f"(v)); return r;
}
__device__ __forceinline__ u32 hmul2u(u32 a, u32 b) {
    u32 d; asm("mul.rn.f16x2 %0,%1,%2;" : "=r"(d) : "r"(a), "r"(b)); return d;
}
__device__ __forceinline__ u32 hfma2u(u32 a, u32 b, u32 c) {
    u32 d; asm("fma.rn.f16x2 %0,%1,%2,%3;" : "=r"(d) : "r"(a), "r"(b), "r"(c)); return d;
}
__device__ __forceinline__ u32 hadd2u(u32 a, u32 b) {
    u32 d; asm("add.rn.f16x2 %0,%1,%2;" : "=r"(d) : "r"(a), "r"(b)); return d;
}
__device__ __forceinline__ u32 prmt(u32 a, u32 sel) {
    u32 d; asm("prmt.b32 %0,%1,%1,%2;" : "=r"(d) : "r"(a), "r"(sel)); return d;
}

#define XSCALE 8.493218003f               // sqrt(50*log2(e)); sp = 50*log2e*|dx|^2
#define CXY   (-0.020037431123458f)       // -log2(e)/72

// half-window exy value: 2*exp(-(di^2+dj^2)/72) inside H, else 0
__device__ __forceinline__ float hw_exy(int di, int dj) {
    if (dj >= -5 && dj <= 5 && (di >= 1 || dj >= 1))
        return 2.0f * __expf(-(float)(di * di + dj * dj) * (1.0f / 72.0f));
    return 0.0f;
}

// column parity swizzle: even cols -> [0,13), odd cols -> [13,26)
__device__ __forceinline__ int swz(int c) { return (c & 1) * 13 + (c >> 1); }

__global__ __launch_bounds__(NT, 3) void crf_fused(const float* __restrict__ x,
                                                   const float* __restrict__ y,
                                                   float* __restrict__ out) {
    __shared__ float4 Ash4[NC];       // scaled (x0,x1,x2,0); OOB cells all-zero
    __shared__ uint4  ysh[3 * NC];    // y fp16 half2 pairs; ch21 slot = in-bounds flag (1.0)
    __shared__ float4 TABP[4 * 18];   // per (g, r*6+m): (0.9*t_pc0, 0.9*t_pc1, 0.1*t_pc0, 0.1*t_pc1)
    __shared__ float  red[8];
    __shared__ int    lastflag;

    const int tid = threadIdx.x;
    const int g   = tid >> 6;         // cell group 0..3: (g&1)=jj parity, (g>>1)=ii parity
    const int gj  = g & 1, gi = g >> 1;
    const int pid = tid & 63;
    const int px  = pid & 7;          // pair col: pixels (2px, 2px+1)
    const int py  = pid >> 3;         // pixel row 0..7
    const int th0 = blockIdx.y * TH, tw0 = blockIdx.x * TW;
    const int bz = blockIdx.z;
    const float* xb = x + (size_t)bz * 3 * PLANE;
    const float* yb = y + (size_t)bz * CYC * PLANE;

    // ---- folded K table ----
    for (int t = tid; t < 72; t += NT) {
        int g2 = t / 18, rem = t - g2 * 18;
        int r = rem / 6, m = rem - r * 6;
        int ii = (g2 >> 1) + 2 * r;
        int jb = (g2 & 1) + 2 * m;
        float t0 = hw_exy(ii, jb - 5);   // pc0 multiplier
        float t1 = hw_exy(ii, jb - 6);   // pc1 multiplier
        TABP[t] = make_float4(0.9f * t0, 0.9f * t1, 0.1f * t0, 0.1f * t1);
    }

    // ---- halo load: x scaled fp32; y fp16-packed with flag channel; OOB zero ----
    for (int cell = tid; cell < NC; cell += NT) {
        int r = cell / HLW, c = cell - r * HLW;
        int gh = th0 + r, gw = tw0 - 5 + c;
        bool v = (gh < HH) && ((unsigned)gw < WW);
        int gidx = gh * WW + gw;
        int dst = r * HLW + swz(c);
        float4 a = make_float4(0.f, 0.f, 0.f, 0.f);
        if (v) {
            a.x = xb[gidx] * XSCALE;
            a.y = xb[PLANE + gidx] * XSCALE;
            a.z = xb[2 * PLANE + gidx] * XSCALE;
        }
        Ash4[dst] = a;
        #pragma unroll
        for (int cg = 0; cg < 3; ++cg) {
            uint4 q = make_uint4(0u, 0u, 0u, 0u);
            if (v) {
                u32 h[4];
                #pragma unroll
                for (int pq = 0; pq < 4; ++pq) {
                    int ch = cg * 8 + pq * 2;
                    float a0 = (ch < CYC) ? yb[ch * PLANE + gidx] : 0.f;
                    float a1 = (ch + 1 < CYC) ? yb[(ch + 1) * PLANE + gidx]
                                              : ((ch + 1 == CYC) ? 1.0f : 0.f);  // flag in ch21
                    __half2 hh = __floats2half2_rn(a0, a1);
                    h[pq] = *(u32*)&hh;
                }
                q.x = h[0]; q.y = h[1]; q.z = h[2]; q.w = h[3];
            }
            ysh[cg * NC + dst] = q;
        }
    }
    __syncthreads();

    // ---- per-thread centers ----
    const int cc0 = py * HLW + swz(2 * px + 5);
    const int cc1 = py * HLW + swz(2 * px + 6);
    u32 yc0[11], yc1[11];
    {
        uint4 a0 = ysh[cc0], b0 = ysh[NC + cc0], c0 = ysh[2 * NC + cc0];
        yc0[0]=a0.x; yc0[1]=a0.y; yc0[2]=a0.z; yc0[3]=a0.w;
        yc0[4]=b0.x; yc0[5]=b0.y; yc0[6]=b0.z; yc0[7]=b0.w;
        yc0[8]=c0.x; yc0[9]=c0.y; yc0[10]=c0.z;
        uint4 a1 = ysh[cc1], b1 = ysh[NC + cc1], c1 = ysh[2 * NC + cc1];
        yc1[0]=a1.x; yc1[1]=a1.y; yc1[2]=a1.z; yc1[3]=a1.w;
        yc1[4]=b1.x; yc1[5]=b1.y; yc1[6]=b1.z; yc1[7]=b1.w;
        yc1[8]=c1.x; yc1[9]=c1.y; yc1[10]=c1.z;
    }
    // overwrite the center's ch21 flag with -1.0 (half 0xBC00): dot' = <y,y> - 1
    yc0[10] = (yc0[10] & 0x0000FFFFu) | 0xBC000000u;
    yc1[10] = (yc1[10] & 0x0000FFFFu) | 0xBC000000u;

    const float4 xc0 = Ash4[cc0];
    const float4 xc1 = Ash4[cc1];
    const u64 ng0 = pack2(-xc0.x, -xc1.x);
    const u64 ng1 = pack2(-xc0.y, -xc1.y);
    const u64 ng2 = pack2(-xc0.z, -xc1.z);
    const u64 cm1 = pack2(-1.0f, -1.0f);

    u32 accP0 = 0u, accP1 = 0u;       // half2 accumulators of K*dot'
    const float4* tabg = TABP + g * 18;
    const int rbase = (py + gi) * HLW + gj * 13 + px;

    // ---- mainloop: 3 rows (ii = gi+2r) x 6 cols (jj = gj+2m) ----
    #pragma unroll
    for (int r = 0; r < 3; ++r) {
        const int rowb = rbase + 2 * r * HLW;
        #pragma unroll
        for (int m = 0; m < 6; ++m) {
            const int cell = rowb + m;
            const float4 cxv = Ash4[cell];
            const uint4 cv0 = ysh[cell];
            const uint4 cv1 = ysh[NC + cell];
            const uint4 cv2 = ysh[2 * NC + cell];
            const float4 ctp = tabg[r * 6 + m];

            // scaled image-diff: sp = 50*log2e*|x_q - x_p|^2, packed over (pc0,pc1)
            u64 d0 = add2(pack2(cxv.x, cxv.x), ng0);
            u64 d1 = add2(pack2(cxv.y, cxv.y), ng1);
            u64 d2 = add2(pack2(cxv.z, cxv.z), ng2);
            u64 sp = mul2(d0, d0); sp = ffma2(d1, d1, sp); sp = ffma2(d2, d2, sp);
            sp = mul2(sp, cm1);
            float ns0, ns1; unpack2(sp, ns0, ns1);
            const float E0 = ex2(ns0), E1 = ex2(ns1);
            const float K0 = fmaf(E0, ctp.x, ctp.z);
            const float K1 = fmaf(E1, ctp.y, ctp.w);
            __half2 kh = __floats2half2_rn(K0, K1);
            const u32 Kp = *(u32*)&kh;
            const u32 Kd0 = prmt(Kp, 0x1010u);   // (K0, K0)
            const u32 Kd1 = prmt(Kp, 0x3232u);   // (K1, K1)

            // dot' chains: 11 half2 terms per pixel, split 6+5
            u32 dp0a = hmul2u(cv0.x, yc0[0]);
            u32 dp1a = hmul2u(cv0.x, yc1[0]);
            u32 dp0b = hmul2u(cv1.z, yc0[6]);
            u32 dp1b = hmul2u(cv1.z, yc1[6]);
            dp0a = hfma2u(cv0.y, yc0[1], dp0a);  dp1a = hfma2u(cv0.y, yc1[1], dp1a);
            dp0b = hfma2u(cv1.w, yc0[7], dp0b);  dp1b = hfma2u(cv1.w, yc1[7], dp1b);
            dp0a = hfma2u(cv0.z, yc0[2], dp0a);  dp1a = hfma2u(cv0.z, yc1[2], dp1a);
            dp0b = hfma2u(cv2.x, yc0[8], dp0b);  dp1b = hfma2u(cv2.x, yc1[8], dp1b);
            dp0a = hfma2u(cv0.w, yc0[3], dp0a);  dp1a = hfma2u(cv0.w, yc1[3], dp1a);
            dp0b = hfma2u(cv2.y, yc0[9], dp0b);  dp1b = hfma2u(cv2.y, yc1[9], dp1b);
            dp0a = hfma2u(cv1.x, yc0[4], dp0a);  dp1a = hfma2u(cv1.x, yc1[4], dp1a);
            dp0b = hfma2u(cv2.z, yc0[10], dp0b); dp1b = hfma2u(cv2.z, yc1[10], dp1b);
            dp0a = hfma2u(cv1.y, yc0[5], dp0a);  dp1a = hfma2u(cv1.y, yc1[5], dp1a);
            const u32 dp0 = hadd2u(dp0a, dp0b);
            const u32 dp1 = hadd2u(dp1a, dp1b);

            accP0 = hfma2u(Kd0, dp0, accP0);
            accP1 = hfma2u(Kd1, dp1, accP1);
        }
    }

    // ---- epilogue: part = -sum(K*dot') + true-OOB closed form ----
    float acc2;
    {
        __half2 a = *(__half2*)&accP0;
        __half2 b = *(__half2*)&accP1;
        acc2 = (__low2float(a) + __high2float(a)) + (__low2float(b) + __high2float(b));
    }
    float acc1 = 0.0f;
    if (g == 0) {
        const int h = th0 + py;
        const int rv = min(5, 127 - h) + min(5, h) + 1;
        #pragma unroll
        for (int pc = 0; pc < 2; ++pc) {
            const int w = tw0 + 2 * px + pc;
            const int cv = min(5, 127 - w) + min(5, w) + 1;
            const int noob = 121 - rv * cv;
            if (noob > 0) {
                const float4 xc = pc ? xc1 : xc0;
                const float sxs = xc.x * xc.x + xc.y * xc.y + xc.z * xc.z;  // scaled
                const float F = fmaf(0.9f, ex2(-sxs), 0.1f);
                acc1 += (float)noob * ex2((float)(h * h + w * w) * CXY) * F;
            }
        }
    }

    // ---- block reduction + fused final reduction (deterministic) ----
    float part = acc1 - acc2;
    #pragma unroll
    for (int o = 16; o > 0; o >>= 1) part += __shfl_xor_sync(0xffffffffu, part, o);
    const int warp = tid >> 5, lane = tid & 31;
    if (lane == 0) red[warp] = part;
    __syncthreads();
    const int bid = ((bz * gridDim.y) + blockIdx.y) * gridDim.x + blockIdx.x;
    if (tid == 0) {
        float s = 0.f;
        #pragma unroll
        for (int wi = 0; wi < 8; ++wi) s += red[wi];
        g_part[bid] = s;
        __threadfence();
        unsigned old = atomicAdd(&g_cnt, 1u);
        lastflag = (old == NBLK - 1) ? 1 : 0;
    }
    __syncthreads();
    if (lastflag) {
        float v = g_part[tid] + g_part[tid + 256];
        #pragma unroll
        for (int o = 16; o > 0; o >>= 1) v += __shfl_xor_sync(0xffffffffu, v, o);
        if (lane == 0) red[warp] = v;
        __syncthreads();
        if (tid == 0) {
            float s = 0.f;
            #pragma unroll
            for (int wi = 0; wi < 8; ++wi) s += red[wi];
            out[0] = s * (1.0f / 65536.0f);
            g_cnt = 0;
        }
    }
}

extern "C" void kernel_launch(void* const* d_in, const int* in_sizes, int n_in,
                              void* d_out, int out_size) {
    const float* x = (const float*)d_in[0];
    const float* y = (const float*)d_in[1];
    (void)in_sizes; (void)n_in; (void)out_size;
    dim3 grid(WW / TW, HH / TH, 4);
    crf_fused<<<grid, NT>>>(x, y, (float*)d_out);
}

// round 11
// speedup vs baseline: 1.1189x; 1.1189x over previous
#include <cuda_runtime.h>
#include <cuda_fp16.h>

#define HH 128
#define WW 128
#define PLANE (HH*WW)
#define CYC 21
#define TW 16
#define TH 8
#define HLW 26              // halo cols: tw0-5 .. tw0+20
#define HLH 13              // halo rows: th0 .. th0+12
#define NC (HLW*HLH)        // 338
#define NT 128              // 64 pixel-pairs x 2 jj-parity groups
#define NBLK 512            // 8*16*4

typedef unsigned long long u64;
typedef unsigned int u32;

__device__ float g_part[NBLK];
__device__ unsigned int g_cnt = 0;

__device__ __forceinline__ float ex2f(float v) {
    float r; asm("ex2.approx.ftz.f32 %0,%1;" : "=f"(r) : "f"(v)); return r;
}
__device__ __forceinline__ u32 hex2(u32 a) {
    u32 d; asm("ex2.approx.f16x2 %0,%1;" : "=r"(d) : "r"(a)); return d;
}
__device__ __forceinline__ u32 hmul2u(u32 a, u32 b) {
    u32 d; asm("mul.rn.f16x2 %0,%1,%2;" : "=r"(d) : "r"(a), "r"(b)); return d;
}
__device__ __forceinline__ u32 hadd2u(u32 a, u32 b) {
    u32 d; asm("add.rn.f16x2 %0,%1,%2;" : "=r"(d) : "r"(a), "r"(b)); return d;
}
__device__ __forceinline__ u32 hfma2u(u32 a, u32 b, u32 c) {
    u32 d; asm("fma.rn.f16x2 %0,%1,%2,%3;" : "=r"(d) : "r"(a), "r"(b), "r"(c)); return d;
}
__device__ __forceinline__ u32 prmt1(u32 a, u32 sel) {
    u32 d; asm("prmt.b32 %0,%1,%1,%2;" : "=r"(d) : "r"(a), "r"(sel)); return d;
}
__device__ __forceinline__ u32 prmt2(u32 a, u32 b, u32 sel) {
    u32 d; asm("prmt.b32 %0,%1,%2,%3;" : "=r"(d) : "r"(a), "r"(b), "r"(sel)); return d;
}

#define XSCALE 8.493218003f               // sqrt(50*log2(e)); s' = 50*log2e*|dx|^2
#define CXY   (-0.020037431123458f)       // -log2(e)/72
#define SGN2  0x80008000u                 // negate both fp16 halves

// half-window exy value: 2*exp(-(di^2+dj^2)/72) inside H, else 0
__device__ __forceinline__ float hw_exy(int di, int dj) {
    if (dj >= -5 && dj <= 5 && (di >= 1 || dj >= 1))
        return 2.0f * __expf(-(float)(di * di + dj * dj) * (1.0f / 72.0f));
    return 0.0f;
}

// column parity swizzle: even cols -> [0,13), odd cols -> [13,26)
__device__ __forceinline__ int swz(int c) { return (c & 1) * 13 + (c >> 1); }

__global__ __launch_bounds__(NT, 4) void crf_fused(const float* __restrict__ x,
                                                   const float* __restrict__ y,
                                                   float* __restrict__ out) {
    __shared__ uint2  xsh[NC];        // scaled x as fp16: (h2(x0,x1), h2(x2,0)); OOB zero
    __shared__ uint4  ysh[3 * NC];    // y fp16 half2 pairs; ch21 slot = in-bounds flag (1.0)
    __shared__ uint2  TABH[2 * 36];   // per (g, idx): (h2(0.9t0,0.9t1), h2(0.1t0,0.1t1))
    __shared__ float  red[4];
    __shared__ int    lastflag;

    const int tid = threadIdx.x;
    const int g   = tid >> 6;         // jj parity group
    const int pid = tid & 63;
    const int px  = pid & 7;          // pair col: pixels (2px, 2px+1)
    const int py  = pid >> 3;         // pixel row 0..7
    const int th0 = blockIdx.y * TH, tw0 = blockIdx.x * TW;
    const int bz = blockIdx.z;
    const float* xb = x + (size_t)bz * 3 * PLANE;
    const float* yb = y + (size_t)bz * CYC * PLANE;

    // ---- folded K table (fp16) ----
    for (int t = tid; t < 72; t += NT) {
        int g2 = t / 36, idx = t - g2 * 36;
        int ii = idx / 6, m = idx - ii * 6;
        float t0 = hw_exy(ii, g2 + 2 * m + 1 - 6);   // pc0 multiplier
        float t1 = hw_exy(ii, g2 + 2 * m - 6);       // pc1 multiplier
        __half2 h9 = __floats2half2_rn(0.9f * t0, 0.9f * t1);
        __half2 h1 = __floats2half2_rn(0.1f * t0, 0.1f * t1);
        TABH[t] = make_uint2(*(u32*)&h9, *(u32*)&h1);
    }

    // ---- halo load: x scaled fp16; y fp16-packed with flag channel; OOB zero ----
    for (int cell = tid; cell < NC; cell += NT) {
        int r = cell / HLW, c = cell - r * HLW;
        int gh = th0 + r, gw = tw0 - 5 + c;
        bool v = (gh < HH) && ((unsigned)gw < WW);
        int gidx = gh * WW + gw;
        int dst = r * HLW + swz(c);
        float x0 = 0.f, x1 = 0.f, x2 = 0.f;
        if (v) {
            x0 = xb[gidx] * XSCALE;
            x1 = xb[PLANE + gidx] * XSCALE;
            x2 = xb[2 * PLANE + gidx] * XSCALE;
        }
        __half2 h01 = __floats2half2_rn(x0, x1);
        __half2 h2f = __floats2half2_rn(x2, 0.f);
        xsh[dst] = make_uint2(*(u32*)&h01, *(u32*)&h2f);
        #pragma unroll
        for (int cg = 0; cg < 3; ++cg) {
            uint4 q = make_uint4(0u, 0u, 0u, 0u);
            if (v) {
                u32 h[4];
                #pragma unroll
                for (int pq = 0; pq < 4; ++pq) {
                    int ch = cg * 8 + pq * 2;
                    float a0 = (ch < CYC) ? yb[ch * PLANE + gidx] : 0.f;
                    float a1 = (ch + 1 < CYC) ? yb[(ch + 1) * PLANE + gidx]
                                              : ((ch + 1 == CYC) ? 1.0f : 0.f);  // flag in ch21
                    __half2 hh = __floats2half2_rn(a0, a1);
                    h[pq] = *(u32*)&hh;
                }
                q.x = h[0]; q.y = h[1]; q.z = h[2]; q.w = h[3];
            }
            ysh[cg * NC + dst] = q;
        }
    }
    __syncthreads();

    // ---- per-thread centers ----
    const int cc0 = py * HLW + swz(2 * px + 5);
    const int cc1 = py * HLW + swz(2 * px + 6);
    u32 yc0[11], yc1[11];
    {
        uint4 a0 = ysh[cc0], b0 = ysh[NC + cc0], c0 = ysh[2 * NC + cc0];
        yc0[0]=a0.x; yc0[1]=a0.y; yc0[2]=a0.z; yc0[3]=a0.w;
        yc0[4]=b0.x; yc0[5]=b0.y; yc0[6]=b0.z; yc0[7]=b0.w;
        yc0[8]=c0.x; yc0[9]=c0.y; yc0[10]=c0.z;
        uint4 a1 = ysh[cc1], b1 = ysh[NC + cc1], c1 = ysh[2 * NC + cc1];
        yc1[0]=a1.x; yc1[1]=a1.y; yc1[2]=a1.z; yc1[3]=a1.w;
        yc1[4]=b1.x; yc1[5]=b1.y; yc1[6]=b1.z; yc1[7]=b1.w;
        yc1[8]=c1.x; yc1[9]=c1.y; yc1[10]=c1.z;
    }
    // overwrite the center's ch21 flag with -1.0 (half 0xBC00): dot' = <y,y> - 1
    yc0[10] = (yc0[10] & 0x0000FFFFu) | 0xBC000000u;
    yc1[10] = (yc1[10] & 0x0000FFFFu) | 0xBC000000u;

    // negated centers, packed per channel over (pc0, pc1)
    const uint2 xq0 = xsh[cc0];
    const uint2 xq1 = xsh[cc1];
    const u32 ng0 = prmt2(xq0.x, xq1.x, 0x5410u) ^ SGN2;   // (-x0_pc0, -x0_pc1)
    const u32 ng1 = prmt2(xq0.x, xq1.x, 0x7632u) ^ SGN2;   // (-x1_pc0, -x1_pc1)
    const u32 ng2 = prmt2(xq0.y, xq1.y, 0x5410u) ^ SGN2;   // (-x2_pc0, -x2_pc1)

    u32 accP0 = 0u, accP1 = 0u;       // half2 accumulators of K*dot'
    const uint2* tabg = TABH + g * 36;
    const int rbase = py * HLW + g * 13 + px;

    // ---- software-pipelined mainloop over 36 cells ----
    uint2  xv = xsh[rbase];
    uint4  v0 = ysh[rbase];
    uint4  v1 = ysh[NC + rbase];
    uint4  v2 = ysh[2 * NC + rbase];
    uint2  tp = tabg[0];

    #pragma unroll
    for (int idx = 0; idx < 36; ++idx) {
        const uint2 cxv = xv;
        const uint4 cv0 = v0, cv1 = v1, cv2 = v2;
        const uint2 ctp = tp;
        if (idx < 35) {
            const int ni = idx + 1;
            const int ncell = rbase + (ni / 6) * HLW + (ni % 6);
            xv = xsh[ncell];
            v0 = ysh[ncell];
            v1 = ysh[NC + ncell];
            v2 = ysh[2 * NC + ncell];
            tp = tabg[ni];
        }

        // s = 50*log2e*|x_q - x_p|^2 in fp16x2, packed over (pc0,pc1)
        const u32 sp0 = prmt1(cxv.x, 0x1010u);       // (x0,x0)
        const u32 sp1 = prmt1(cxv.x, 0x3232u);       // (x1,x1)
        const u32 sp2 = prmt1(cxv.y, 0x1010u);       // (x2,x2)
        const u32 d0 = hadd2u(sp0, ng0);
        const u32 d1 = hadd2u(sp1, ng1);
        const u32 d2 = hadd2u(sp2, ng2);
        u32 s = hmul2u(d0, d0);
        s = hfma2u(d1, d1, s);
        s = hfma2u(d2, d2, s);
        const u32 E = hex2(s ^ SGN2);                // (2^-s_pc0, 2^-s_pc1)
        const u32 Kh = hfma2u(E, ctp.x, ctp.y);      // (K_pc0, K_pc1)
        const u32 Kd0 = prmt1(Kh, 0x1010u);          // (K0, K0)
        const u32 Kd1 = prmt1(Kh, 0x3232u);          // (K1, K1)

        // dot' chains: 11 half2 terms per pixel, split 6+5
        u32 dp0a = hmul2u(cv0.x, yc0[0]);
        u32 dp1a = hmul2u(cv0.x, yc1[0]);
        u32 dp0b = hmul2u(cv1.z, yc0[6]);
        u32 dp1b = hmul2u(cv1.z, yc1[6]);
        dp0a = hfma2u(cv0.y, yc0[1], dp0a);  dp1a = hfma2u(cv0.y, yc1[1], dp1a);
        dp0b = hfma2u(cv1.w, yc0[7], dp0b);  dp1b = hfma2u(cv1.w, yc1[7], dp1b);
        dp0a = hfma2u(cv0.z, yc0[2], dp0a);  dp1a = hfma2u(cv0.z, yc1[2], dp1a);
        dp0b = hfma2u(cv2.x, yc0[8], dp0b);  dp1b = hfma2u(cv2.x, yc1[8], dp1b);
        dp0a = hfma2u(cv0.w, yc0[3], dp0a);  dp1a = hfma2u(cv0.w, yc1[3], dp1a);
        dp0b = hfma2u(cv2.y, yc0[9], dp0b);  dp1b = hfma2u(cv2.y, yc1[9], dp1b);
        dp0a = hfma2u(cv1.x, yc0[4], dp0a);  dp1a = hfma2u(cv1.x, yc1[4], dp1a);
        dp0b = hfma2u(cv2.z, yc0[10], dp0b); dp1b = hfma2u(cv2.z, yc1[10], dp1b);
        dp0a = hfma2u(cv1.y, yc0[5], dp0a);  dp1a = hfma2u(cv1.y, yc1[5], dp1a);
        const u32 dp0 = hadd2u(dp0a, dp0b);
        const u32 dp1 = hadd2u(dp1a, dp1b);

        accP0 = hfma2u(Kd0, dp0, accP0);
        accP1 = hfma2u(Kd1, dp1, accP1);
    }

    // ---- epilogue: part = -sum(K*dot') + true-OOB closed form ----
    float acc2;
    {
        __half2 a = *(__half2*)&accP0;
        __half2 b = *(__half2*)&accP1;
        acc2 = (__low2float(a) + __high2float(a)) + (__low2float(b) + __high2float(b));
    }
    float acc1 = 0.0f;
    if (g == 0) {
        // |x_c'|^2 packed (pc0,pc1) from negated centers (sign squares away)
        u32 sxs = hmul2u(ng0, ng0);
        sxs = hfma2u(ng1, ng1, sxs);
        sxs = hfma2u(ng2, ng2, sxs);
        const u32 Ex = hex2(sxs ^ SGN2);
        const __half2 Exh = *(__half2*)&Ex;
        const int h = th0 + py;
        const int rv = min(5, 127 - h) + min(5, h) + 1;
        #pragma unroll
        for (int pc = 0; pc < 2; ++pc) {
            const int w = tw0 + 2 * px + pc;
            const int cv = min(5, 127 - w) + min(5, w) + 1;
            const int noob = 121 - rv * cv;
            if (noob > 0) {
                const float Ec = pc ? __high2float(Exh) : __low2float(Exh);
                const float F = fmaf(0.9f, Ec, 0.1f);
                acc1 += (float)noob * ex2f((float)(h * h + w * w) * CXY) * F;
            }
        }
    }

    // ---- block reduction + fused final reduction (deterministic) ----
    float part = acc1 - acc2;
    #pragma unroll
    for (int o = 16; o > 0; o >>= 1) part += __shfl_xor_sync(0xffffffffu, part, o);
    const int warp = tid >> 5, lane = tid & 31;
    if (lane == 0) red[warp] = part;
    __syncthreads();
    const int bid = ((bz * gridDim.y) + blockIdx.y) * gridDim.x + blockIdx.x;
    if (tid == 0) {
        g_part[bid] = (red[0] + red[1]) + (red[2] + red[3]);
        __threadfence();
        unsigned old = atomicAdd(&g_cnt, 1u);
        lastflag = (old == NBLK - 1) ? 1 : 0;
    }
    __syncthreads();
    if (lastflag) {
        float v = (g_part[tid] + g_part[tid + 128]) +
                  (g_part[tid + 256] + g_part[tid + 384]);
        #pragma unroll
        for (int o = 16; o > 0; o >>= 1) v += __shfl_xor_sync(0xffffffffu, v, o);
        if (lane == 0) red[warp] = v;
        __syncthreads();
        if (tid == 0) {
            out[0] = ((red[0] + red[1]) + (red[2] + red[3])) * (1.0f / 65536.0f);
            g_cnt = 0;
        }
    }
}

extern "C" void kernel_launch(void* const* d_in, const int* in_sizes, int n_in,
                              void* d_out, int out_size) {
    const float* x = (const float*)d_in[0];
    const float* y = (const float*)d_in[1];
    (void)in_sizes; (void)n_in; (void)out_size;
    dim3 grid(WW / TW, HH / TH, 4);
    crf_fused<<<grid, NT>>>(x, y, (float*)d_out);
}